// round 16
// baseline (speedup 1.0000x reference)
#include <cuda_runtime.h>
#include <cstdint>

#define HDIM 4096
#define THREADS 256
#define NWARPS (THREADS / 32)
#define ELEMS_PER_THREAD (HDIM / THREADS)   // 16
#define VEC 4                               // floats per float4
#define NITER (ELEMS_PER_THREAD / VEC)      // 4
#define EPSF 1e-6f

__global__ __launch_bounds__(THREADS) void qrmsnorm_kernel(
    const float* __restrict__ x,
    const float* __restrict__ w,
    float* __restrict__ q_out,      // quantized values emitted as float32
    float* __restrict__ scale_out)
{
    const int row = blockIdx.x;
    const float* xr = x + (size_t)row * HDIM;
    const int tid = threadIdx.x;

    float xw[ELEMS_PER_THREAD];
    float sumsq = 0.0f;
    float maxa  = 0.0f;

    // Single pass: streaming (non-temporal) x loads, cached weight loads.
    // Keep x*w in regs; jointly accumulate sum(x^2) and max|x*w|.
    #pragma unroll
    for (int i = 0; i < NITER; i++) {
        const int base = (i * THREADS + tid) * VEC;
        float4 xv = __ldcs(reinterpret_cast<const float4*>(xr + base));
        float4 wv = __ldg (reinterpret_cast<const float4*>(w  + base));
        const float* xf = &xv.x;
        const float* wf = &wv.x;
        #pragma unroll
        for (int j = 0; j < VEC; j++) {
            sumsq = fmaf(xf[j], xf[j], sumsq);
            float p = xf[j] * wf[j];
            xw[i * VEC + j] = p;
            maxa = fmaxf(maxa, fabsf(p));
        }
    }

    // Warp reduction of (sumsq, maxa).
    #pragma unroll
    for (int o = 16; o > 0; o >>= 1) {
        sumsq += __shfl_xor_sync(0xffffffffu, sumsq, o);
        maxa   = fmaxf(maxa, __shfl_xor_sync(0xffffffffu, maxa, o));
    }

    // Single-barrier block reduction: per-warp partials to smem, one sync,
    // then every thread reduces the NWARPS partials locally.
    __shared__ float s_sum[NWARPS];
    __shared__ float s_max[NWARPS];

    const int warp = tid >> 5;
    const int lane = tid & 31;
    if (lane == 0) { s_sum[warp] = sumsq; s_max[warp] = maxa; }
    __syncthreads();

    float total  = s_sum[0];
    float maxtot = s_max[0];
    #pragma unroll
    for (int k = 1; k < NWARPS; k++) {
        total  += s_sum[k];
        maxtot  = fmaxf(maxtot, s_max[k]);
    }

    const float rstd  = rsqrtf(total * (1.0f / HDIM) + EPSF);
    const float scale = rstd * maxtot * (1.0f / 127.0f);
    if (tid == 0) scale_out[row] = scale;

    // q = clip(round(x*w*rstd / scale)) = clip(round(x*w * 127/max|x*w|))
    const float r = 127.0f / fmaxf(maxtot, 1e-30f);

    float* qr = q_out + (size_t)row * HDIM;
    #pragma unroll
    for (int i = 0; i < NITER; i++) {
        const int base = (i * THREADS + tid) * VEC;
        float4 o;
        float* ov = &o.x;
        #pragma unroll
        for (int j = 0; j < VEC; j++) {
            float v = rintf(xw[i * VEC + j] * r);
            ov[j] = fminf(fmaxf(v, -128.0f), 127.0f);
        }
        __stcs(reinterpret_cast<float4*>(qr + base), o);
    }
}

extern "C" void kernel_launch(void* const* d_in, const int* in_sizes, int n_in,
                              void* d_out, int out_size)
{
    const float* x = (const float*)d_in[0];   // hidden_states [B,S,H] (fp32)
    const float* w = (const float*)d_in[1];   // weight [H]

    const long long total_elems = (long long)in_sizes[0];    // B*S*H
    const int h = in_sizes[1];                                // H = 4096
    const int n_rows = (int)(total_elems / h);                // B*S = 16384

    float* q = (float*)d_out;                                 // output 0: q as fp32
    // output 1: per-token scales, last n_rows float32 elements of d_out
    float* scale = (float*)d_out + ((long long)out_size - n_rows);

    qrmsnorm_kernel<<<n_rows, THREADS>>>(x, w, q, scale);
}

// round 17
// speedup vs baseline: 1.0016x; 1.0016x over previous
#include <cuda_runtime.h>
#include <cstdint>

#define HDIM 4096
#define THREADS 256
#define NWARPS (THREADS / 32)
#define ELEMS_PER_THREAD (HDIM / THREADS)   // 16
#define VEC 4                               // floats per float4
#define NITER (ELEMS_PER_THREAD / VEC)      // 4
#define EPSF 1e-6f

__global__ __launch_bounds__(THREADS) void qrmsnorm_kernel(
    const float* __restrict__ x,
    const float* __restrict__ w,
    float* __restrict__ q_out,      // quantized values emitted as float32
    float* __restrict__ scale_out)
{
    const int row = blockIdx.x;
    const float* xr = x + (size_t)row * HDIM;
    const int tid = threadIdx.x;

    float xw[ELEMS_PER_THREAD];
    float sumsq = 0.0f;
    float maxa  = 0.0f;

    // Single pass: streaming (non-temporal) x loads, cached weight loads.
    // Keep x*w in regs; jointly accumulate sum(x^2) and max|x*w|.
    #pragma unroll
    for (int i = 0; i < NITER; i++) {
        const int base = (i * THREADS + tid) * VEC;
        float4 xv = __ldcs(reinterpret_cast<const float4*>(xr + base));
        float4 wv = __ldg (reinterpret_cast<const float4*>(w  + base));
        const float* xf = &xv.x;
        const float* wf = &wv.x;
        #pragma unroll
        for (int j = 0; j < VEC; j++) {
            sumsq = fmaf(xf[j], xf[j], sumsq);
            float p = xf[j] * wf[j];
            xw[i * VEC + j] = p;
            maxa = fmaxf(maxa, fabsf(p));
        }
    }

    // Warp reduction of (sumsq, maxa).
    #pragma unroll
    for (int o = 16; o > 0; o >>= 1) {
        sumsq += __shfl_xor_sync(0xffffffffu, sumsq, o);
        maxa   = fmaxf(maxa, __shfl_xor_sync(0xffffffffu, maxa, o));
    }

    // Single-barrier block reduction: per-warp partials to smem, one sync,
    // then every thread reduces the NWARPS partials locally.
    __shared__ float s_sum[NWARPS];
    __shared__ float s_max[NWARPS];

    const int warp = tid >> 5;
    const int lane = tid & 31;
    if (lane == 0) { s_sum[warp] = sumsq; s_max[warp] = maxa; }
    __syncthreads();

    float total  = s_sum[0];
    float maxtot = s_max[0];
    #pragma unroll
    for (int k = 1; k < NWARPS; k++) {
        total  += s_sum[k];
        maxtot  = fmaxf(maxtot, s_max[k]);
    }

    const float rstd  = rsqrtf(total * (1.0f / HDIM) + EPSF);
    const float scale = rstd * maxtot * (1.0f / 127.0f);
    if (tid == 0) scale_out[row] = scale;

    // q = clip(round(x*w*rstd / scale)) = clip(round(x*w * 127/max|x*w|))
    const float r = 127.0f / fmaxf(maxtot, 1e-30f);

    float* qr = q_out + (size_t)row * HDIM;
    #pragma unroll
    for (int i = 0; i < NITER; i++) {
        const int base = (i * THREADS + tid) * VEC;
        float4 o;
        float* ov = &o.x;
        #pragma unroll
        for (int j = 0; j < VEC; j++) {
            float v = rintf(xw[i * VEC + j] * r);
            ov[j] = fminf(fmaxf(v, -128.0f), 127.0f);
        }
        __stcs(reinterpret_cast<float4*>(qr + base), o);
    }
}

extern "C" void kernel_launch(void* const* d_in, const int* in_sizes, int n_in,
                              void* d_out, int out_size)
{
    const float* x = (const float*)d_in[0];   // hidden_states [B,S,H] (fp32)
    const float* w = (const float*)d_in[1];   // weight [H]

    const long long total_elems = (long long)in_sizes[0];    // B*S*H
    const int h = in_sizes[1];                                // H = 4096
    const int n_rows = (int)(total_elems / h);                // B*S = 16384

    float* q = (float*)d_out;                                 // output 0: q as fp32
    // output 1: per-token scales, last n_rows float32 elements of d_out
    float* scale = (float*)d_out + ((long long)out_size - n_rows);

    qrmsnorm_kernel<<<n_rows, THREADS>>>(x, w, q, scale);
}